// round 1
// baseline (speedup 1.0000x reference)
#include <cuda_runtime.h>
#include <cstdint>

// Problem constants
#define BB 1024
#define TT 200
#define EE 128
#define HH 64
#define TTILE 64
#define NTHREADS 256

// Shared memory layout (floats):
//  [0,128)      q_s
//  [128,192)    A_s
//  [192,448)    Ap (4 partial A slices)
//  [448,8640)   M_s  [128][64]
//  [8640,16832) k_s  [64][128]
#define SMEM_FLOATS 16832
#define SMEM_BYTES (SMEM_FLOATS * 4)

typedef unsigned long long u64;

__device__ __forceinline__ u64 pack2(float x, float y) {
    u64 r;
    asm("mov.b64 %0, {%1,%2};" : "=l"(r) : "f"(x), "f"(y));
    return r;
}

__device__ __forceinline__ void unpack2(u64 v, float& x, float& y) {
    asm("mov.b64 {%0,%1}, %2;" : "=f"(x), "=f"(y) : "l"(v));
}

__device__ __forceinline__ u64 fma2(u64 a, u64 b, u64 c) {
    u64 d;
    asm("fma.rn.f32x2 %0, %1, %2, %3;" : "=l"(d) : "l"(a), "l"(b), "l"(c));
    return d;
}

__global__ void __launch_bounds__(NTHREADS)
lau_kernel(const float* __restrict__ query,
           const float* __restrict__ keys,
           const float* __restrict__ W0,
           const float* __restrict__ b0,
           const float* __restrict__ W1,
           const float* __restrict__ b1,
           float* __restrict__ out)
{
    extern __shared__ float sm[];
    float* q_s = sm;            // 128
    float* A_s = sm + 128;      // 64
    float* Ap  = sm + 192;      // 256
    float* M_s = sm + 448;      // 128*64
    float* k_s = sm + 8640;     // 64*128

    const int b   = blockIdx.x;
    const int tid = threadIdx.x;

    // ---- Phase 0: load q[b] ----
    if (tid < EE) q_s[tid] = query[(size_t)b * EE + tid];
    __syncthreads();

    // ---- Phase 1a: M[e][h] = W0b - W0c + q_e * W0d ----
    #pragma unroll 4
    for (int idx = tid; idx < EE * HH; idx += NTHREADS) {
        const int e = idx >> 6;
        const int h = idx & 63;
        const float qe = q_s[e];
        M_s[idx] = W0[(128 + e) * 64 + h] - W0[(256 + e) * 64 + h]
                 + qe * W0[(384 + e) * 64 + h];
    }

    // ---- Phase 1b: A[h] = b0[h] + q @ (W0a + W0c), split over 4 e-slices ----
    {
        const int h = tid & 63;
        const int p = tid >> 6;        // 0..3
        float a = 0.f;
        const int e0 = p * 32;
        #pragma unroll 8
        for (int e = e0; e < e0 + 32; ++e)
            a += q_s[e] * (W0[e * 64 + h] + W0[(256 + e) * 64 + h]);
        Ap[p * 64 + h] = a;
    }
    __syncthreads();
    if (tid < HH)
        A_s[tid] = b0[tid] + Ap[tid] + Ap[64 + tid] + Ap[128 + tid] + Ap[192 + tid];
    __syncthreads();

    // ---- Phase 2: per-batch GEMM h_pre = A + K @ M, fused relu + dot(W1) ----
    const int tx = tid & 15;       // h-group: h0 = 4*tx
    const int ty = tid >> 4;       // t-group: tr = 4*ty within tile
    const int h0 = tx * 4;
    const int tr = ty * 4;

    float w1v[4];
    #pragma unroll
    for (int j = 0; j < 4; ++j) w1v[j] = W1[h0 + j];
    const float bias1 = b1[0];

    for (int t0 = 0; t0 < 4 * TTILE; t0 += TTILE) {
        // load k tile [64][128] (zeros past T)
        #pragma unroll 2
        for (int idx = tid; idx < TTILE * (EE / 4); idx += NTHREADS) {
            const int row = idx >> 5;
            const int c4  = idx & 31;
            const int t   = t0 + row;
            float4 v = make_float4(0.f, 0.f, 0.f, 0.f);
            if (t < TT)
                v = *(const float4*)(keys + ((size_t)b * TT + t) * EE + c4 * 4);
            *(float4*)(k_s + row * EE + c4 * 4) = v;
        }
        __syncthreads();

        // accumulators: 4 t-rows x 2 packed h-pairs, init from A
        const ulonglong2 ainit = *(const ulonglong2*)(A_s + h0);
        u64 acc0[4], acc1[4];
        #pragma unroll
        for (int i = 0; i < 4; ++i) { acc0[i] = ainit.x; acc1[i] = ainit.y; }

        #pragma unroll 4
        for (int e = 0; e < EE; e += 4) {
            // M operand pairs, loaded directly as 64-bit words (no packing)
            ulonglong2 m0 = *(const ulonglong2*)(M_s + (e + 0) * HH + h0);
            ulonglong2 m1 = *(const ulonglong2*)(M_s + (e + 1) * HH + h0);
            ulonglong2 m2 = *(const ulonglong2*)(M_s + (e + 2) * HH + h0);
            ulonglong2 m3 = *(const ulonglong2*)(M_s + (e + 3) * HH + h0);
            #pragma unroll
            for (int i = 0; i < 4; ++i) {
                const float4 kv = *(const float4*)(k_s + (tr + i) * EE + e);
                u64 k0 = pack2(kv.x, kv.x);
                u64 k1 = pack2(kv.y, kv.y);
                u64 k2 = pack2(kv.z, kv.z);
                u64 k3 = pack2(kv.w, kv.w);
                acc0[i] = fma2(k0, m0.x, acc0[i]);
                acc1[i] = fma2(k0, m0.y, acc1[i]);
                acc0[i] = fma2(k1, m1.x, acc0[i]);
                acc1[i] = fma2(k1, m1.y, acc1[i]);
                acc0[i] = fma2(k2, m2.x, acc0[i]);
                acc1[i] = fma2(k2, m2.y, acc1[i]);
                acc0[i] = fma2(k3, m3.x, acc0[i]);
                acc1[i] = fma2(k3, m3.y, acc1[i]);
            }
        }

        // epilogue: relu, dot with W1, reduce over the 16 h-group lanes
        float sc[4];
        #pragma unroll
        for (int i = 0; i < 4; ++i) {
            float c0, c1, c2, c3;
            unpack2(acc0[i], c0, c1);
            unpack2(acc1[i], c2, c3);
            sc[i] = fmaxf(c0, 0.f) * w1v[0] + fmaxf(c1, 0.f) * w1v[1]
                  + fmaxf(c2, 0.f) * w1v[2] + fmaxf(c3, 0.f) * w1v[3];
        }
        #pragma unroll
        for (int m = 1; m < 16; m <<= 1) {
            #pragma unroll
            for (int i = 0; i < 4; ++i)
                sc[i] += __shfl_xor_sync(0xffffffffu, sc[i], m);
        }
        if (tx == 0) {
            #pragma unroll
            for (int i = 0; i < 4; ++i) {
                const int t = t0 + tr + i;
                if (t < TT)
                    out[(size_t)b * TT + t] = sc[i] + bias1;
            }
        }
        __syncthreads();   // k_s reused next tile
    }
}

extern "C" void kernel_launch(void* const* d_in, const int* in_sizes, int n_in,
                              void* d_out, int out_size)
{
    const float* query = (const float*)d_in[0];
    const float* keys  = (const float*)d_in[1];
    const float* W0    = (const float*)d_in[2];
    const float* b0    = (const float*)d_in[3];
    const float* W1    = (const float*)d_in[4];
    const float* b1    = (const float*)d_in[5];
    float* out = (float*)d_out;

    static bool attr_set = false;
    if (!attr_set) {
        cudaFuncSetAttribute(lau_kernel,
                             cudaFuncAttributeMaxDynamicSharedMemorySize,
                             SMEM_BYTES);
        attr_set = true;
    }

    lau_kernel<<<BB, NTHREADS, SMEM_BYTES>>>(query, keys, W0, b0, W1, b1, out);
}

// round 3
// speedup vs baseline: 1.6468x; 1.6468x over previous
#include <cuda_runtime.h>
#include <cstdint>

#define BB 1024
#define TT 200
#define EE 128
#define HH 64
#define NTHREADS 256

// ---- smem layout (float offsets) ----
#define SM_Q   0          // 128 floats
#define SM_AW  128        // 64 float2
#define SM_AP  256        // 4*64 partial A
#define SM_BF  512        // float4[16][4][32] = 8192 floats (B fragments)
#define SM_AS  8704       // keys tile: 112 rows * 132 floats (padded)
#define SMEM_FLOATS (8704 + 112*132)
#define SMEM_BYTES  (SMEM_FLOATS * 4)

__device__ __forceinline__ float to_tf32(float x) {
    float r; asm("cvt.rna.tf32.f32 %0, %1;" : "=f"(r) : "f"(x)); return r;
}

__device__ __forceinline__ void mma8(float c[4], const uint32_t a[4],
                                     uint32_t b0, uint32_t b1) {
    asm volatile(
        "mma.sync.aligned.m16n8k8.row.col.f32.tf32.tf32.f32 "
        "{%0,%1,%2,%3}, {%4,%5,%6,%7}, {%8,%9}, {%0,%1,%2,%3};"
        : "+f"(c[0]), "+f"(c[1]), "+f"(c[2]), "+f"(c[3])
        : "r"(a[0]), "r"(a[1]), "r"(a[2]), "r"(a[3]), "r"(b0), "r"(b1));
}

__global__ void __launch_bounds__(NTHREADS, 2)
lau_mma_kernel(const float* __restrict__ query,
               const float* __restrict__ keys,
               const float* __restrict__ W0,
               const float* __restrict__ b0v,
               const float* __restrict__ W1,
               const float* __restrict__ b1v,
               float* __restrict__ out)
{
    extern __shared__ float sm[];
    float*  q_s = sm + SM_Q;
    float2* aw  = (float2*)(sm + SM_AW);
    float*  ap  = sm + SM_AP;
    float*  bf  = sm + SM_BF;
    float*  as_ = sm + SM_AS;

    const int cta  = blockIdx.x;
    const int b    = cta >> 1;
    const int half = cta & 1;
    const int t0   = half ? 96 : 0;
    const int rows = half ? 104 : 96;   // real key rows this CTA
    const int nblk = half ? 7 : 6;      // m16 blocks
    const int npad = nblk * 16;

    const int tid = threadIdx.x;

    // ---- q ----
    if (tid < EE) q_s[tid] = __ldg(query + (size_t)b * EE + tid);
    __syncthreads();

    // ---- keys -> As (tf32, row pad 132) ----
    const float* kb = keys + ((size_t)b * TT + t0) * EE;
    #pragma unroll 4
    for (int idx = tid; idx < npad * 32; idx += NTHREADS) {
        const int r  = idx >> 5;
        const int c4 = idx & 31;
        float4 v = make_float4(0.f, 0.f, 0.f, 0.f);
        if (r < rows) v = __ldg((const float4*)(kb + r * EE) + c4);
        v.x = to_tf32(v.x); v.y = to_tf32(v.y);
        v.z = to_tf32(v.z); v.w = to_tf32(v.w);
        *(float4*)(as_ + r * 132 + c4 * 4) = v;
    }

    // ---- B fragments: Bf[k][p][lane] = {M[e0][h0],M[e1][h0],M[e0][h1],M[e1][h1]} ----
    // M[e][h] = W0b[e][h] - W0c[e][h] + q[e]*W0d[e][h]
    #pragma unroll 2
    for (int idx = tid; idx < 2048; idx += NTHREADS) {
        const int k  = idx >> 7;
        const int p  = (idx >> 5) & 3;
        const int l  = idx & 31;
        const int g  = l >> 2;
        const int tg = l & 3;
        const int e0 = k * 8 + tg, e1 = e0 + 4;
        const int h0 = p * 16 + g, h1 = h0 + 8;
        const float q0 = q_s[e0], q1 = q_s[e1];
        float4 v;
        v.x = to_tf32(__ldg(W0 + (128 + e0) * 64 + h0) - __ldg(W0 + (256 + e0) * 64 + h0)
                      + q0 * __ldg(W0 + (384 + e0) * 64 + h0));
        v.y = to_tf32(__ldg(W0 + (128 + e1) * 64 + h0) - __ldg(W0 + (256 + e1) * 64 + h0)
                      + q1 * __ldg(W0 + (384 + e1) * 64 + h0));
        v.z = to_tf32(__ldg(W0 + (128 + e0) * 64 + h1) - __ldg(W0 + (256 + e0) * 64 + h1)
                      + q0 * __ldg(W0 + (384 + e0) * 64 + h1));
        v.w = to_tf32(__ldg(W0 + (128 + e1) * 64 + h1) - __ldg(W0 + (256 + e1) * 64 + h1)
                      + q1 * __ldg(W0 + (384 + e1) * 64 + h1));
        *(float4*)(bf + idx * 4) = v;
    }

    // ---- A partials: A[h] = b0[h] + q . (W0a[:,h] + W0c[:,h]) ----
    {
        const int h = tid & 63;
        const int p = tid >> 6;
        float s = 0.f;
        #pragma unroll 8
        for (int e = p * 32; e < p * 32 + 32; ++e)
            s = fmaf(q_s[e], __ldg(W0 + e * 64 + h) + __ldg(W0 + (256 + e) * 64 + h), s);
        ap[p * 64 + h] = s;
    }
    __syncthreads();
    if (tid < HH)
        aw[tid] = make_float2(__ldg(b0v + tid) + ap[tid] + ap[64 + tid]
                              + ap[128 + tid] + ap[192 + tid],
                              __ldg(W1 + tid));
    __syncthreads();

    // ---- compute: one m16 block per warp ----
    const int wid = tid >> 5;
    const int lid = tid & 31;
    if (wid < nblk) {
        const int g  = lid >> 2;
        const int tg = lid & 3;
        const int m0 = wid * 16;

        float acc[8][4];
        #pragma unroll
        for (int j = 0; j < 8; ++j)
            #pragma unroll
            for (int i = 0; i < 4; ++i) acc[j][i] = 0.f;

        const uint32_t* asu = (const uint32_t*)as_;
        const uint32_t* bfu = (const uint32_t*)bf;
        const int rowA = (m0 + g) * 132;

        #pragma unroll
        for (int k = 0; k < 16; ++k) {
            uint32_t a[4];
            const int col = k * 8 + tg;
            a[0] = asu[rowA + col];
            a[1] = asu[rowA + 8 * 132 + col];
            a[2] = asu[rowA + col + 4];
            a[3] = asu[rowA + 8 * 132 + col + 4];
            #pragma unroll
            for (int p = 0; p < 4; ++p) {
                const uint4 bv = *(const uint4*)(bfu + ((k * 4 + p) * 32 + lid) * 4);
                mma8(acc[2 * p],     a, bv.x, bv.y);
                mma8(acc[2 * p + 1], a, bv.z, bv.w);
            }
        }

        // ---- fused epilogue ----
        const float bias1 = __ldg(b1v);
        float s0 = bias1, s1 = bias1;
        #pragma unroll
        for (int j = 0; j < 8; ++j) {
            const int h = j * 8 + 2 * tg;
            const float2 w0 = aw[h];
            const float2 w1 = aw[h + 1];
            s0 = fmaf(fmaxf(acc[j][0] + w0.x, 0.f), w0.y, s0);
            s0 = fmaf(fmaxf(acc[j][1] + w1.x, 0.f), w1.y, s0);
            s1 = fmaf(fmaxf(acc[j][2] + w0.x, 0.f), w0.y, s1);
            s1 = fmaf(fmaxf(acc[j][3] + w1.x, 0.f), w1.y, s1);
        }
        s0 += __shfl_xor_sync(0xffffffffu, s0, 1);
        s0 += __shfl_xor_sync(0xffffffffu, s0, 2);
        s1 += __shfl_xor_sync(0xffffffffu, s1, 1);
        s1 += __shfl_xor_sync(0xffffffffu, s1, 2);
        if (tg == 0) {
            const int t = t0 + m0 + g;
            if (t < TT)     out[(size_t)b * TT + t]     = s0;
            if (t + 8 < TT) out[(size_t)b * TT + t + 8] = s1;
        }
    }
}

extern "C" void kernel_launch(void* const* d_in, const int* in_sizes, int n_in,
                              void* d_out, int out_size)
{
    const float* query = (const float*)d_in[0];
    const float* keys  = (const float*)d_in[1];
    const float* W0    = (const float*)d_in[2];
    const float* b0    = (const float*)d_in[3];
    const float* W1    = (const float*)d_in[4];
    const float* b1    = (const float*)d_in[5];
    float* out = (float*)d_out;

    cudaFuncSetAttribute(lau_mma_kernel,
                         cudaFuncAttributeMaxDynamicSharedMemorySize, SMEM_BYTES);

    lau_mma_kernel<<<2 * BB, NTHREADS, SMEM_BYTES>>>(query, keys, W0, b0, W1, b1, out);
}

// round 6
// speedup vs baseline: 2.0705x; 1.2573x over previous
#include <cuda_runtime.h>
#include <cstdint>

#define BB 1024
#define TT 200
#define EE 128
#define HH 64
#define NTHREADS 256

// ---- prepped weights (built once per launch by prep_kernel) ----
__device__ float4 g_bcF[2048];   // (W0b - W0c) in B-fragment order [k][p][lane]
__device__ float4 g_dF [2048];   // (W0d)       in B-fragment order
__device__ float  g_ac [8192];   // (W0a + W0c) natural [e][h] order

__global__ void prep_kernel(const float* __restrict__ W0) {
    const int i = blockIdx.x * blockDim.x + threadIdx.x;   // 8192 threads
    if (i < 8192) {
        const int e = i >> 6, h = i & 63;
        g_ac[i] = __ldg(W0 + e * 64 + h) + __ldg(W0 + (256 + e) * 64 + h);
    }
    if (i < 2048) {
        const int k = i >> 7;
        const int p = (i >> 5) & 3;
        const int l = i & 31;
        const int g = l >> 2, tg = l & 3;
        const int e0 = k * 8 + tg, e1 = e0 + 4;
        const int h0 = p * 16 + g, h1 = h0 + 8;
        float4 bc, dd;
        bc.x = __ldg(W0 + (128 + e0) * 64 + h0) - __ldg(W0 + (256 + e0) * 64 + h0);
        bc.y = __ldg(W0 + (128 + e1) * 64 + h0) - __ldg(W0 + (256 + e1) * 64 + h0);
        bc.z = __ldg(W0 + (128 + e0) * 64 + h1) - __ldg(W0 + (256 + e0) * 64 + h1);
        bc.w = __ldg(W0 + (128 + e1) * 64 + h1) - __ldg(W0 + (256 + e1) * 64 + h1);
        dd.x = __ldg(W0 + (384 + e0) * 64 + h0);
        dd.y = __ldg(W0 + (384 + e1) * 64 + h0);
        dd.z = __ldg(W0 + (384 + e0) * 64 + h1);
        dd.w = __ldg(W0 + (384 + e1) * 64 + h1);
        g_bcF[i] = bc;
        g_dF[i]  = dd;
    }
}

// ---- smem layout (float offsets) ----
#define SM_Q   0          // 128 floats
#define SM_AW  128        // 64 float2
#define SM_AP  256        // 4*64 partial A
#define SM_BF  512        // float4[16][4][32] = 8192 floats (B fragments)
#define SM_AS  8704       // keys tile: 112 rows * 132 floats (padded)
#define SMEM_FLOATS (8704 + 112*132)
#define SMEM_BYTES  (SMEM_FLOATS * 4)

__device__ __forceinline__ float to_tf32(float x) {
    float r; asm("cvt.rna.tf32.f32 %0, %1;" : "=f"(r) : "f"(x)); return r;
}

__device__ __forceinline__ void mma8(float c[4], const uint32_t a[4],
                                     uint32_t b0, uint32_t b1) {
    asm volatile(
        "mma.sync.aligned.m16n8k8.row.col.f32.tf32.tf32.f32 "
        "{%0,%1,%2,%3}, {%4,%5,%6,%7}, {%8,%9}, {%0,%1,%2,%3};"
        : "+f"(c[0]), "+f"(c[1]), "+f"(c[2]), "+f"(c[3])
        : "r"(a[0]), "r"(a[1]), "r"(a[2]), "r"(a[3]), "r"(b0), "r"(b1));
}

__global__ void __launch_bounds__(NTHREADS, 2)
lau_mma_kernel(const float* __restrict__ query,
               const float* __restrict__ keys,
               const float* __restrict__ b0v,
               const float* __restrict__ W1,
               const float* __restrict__ b1v,
               float* __restrict__ out)
{
    extern __shared__ float sm[];
    float*  q_s = sm + SM_Q;
    float2* aw  = (float2*)(sm + SM_AW);
    float*  ap  = sm + SM_AP;
    float*  bf  = sm + SM_BF;
    float*  as_ = sm + SM_AS;

    const int cta  = blockIdx.x;
    const int b    = cta >> 1;
    const int half = cta & 1;
    const int t0   = half ? 96 : 0;
    const int rows = half ? 104 : 96;   // real key rows this CTA
    const int nblk = half ? 7 : 6;      // m16 blocks
    const int npad = nblk * 16;

    const int tid = threadIdx.x;

    // ---- q ----
    if (tid < EE) q_s[tid] = __ldg(query + (size_t)b * EE + tid);
    __syncthreads();

    // ---- keys -> As (tf32, row pad 132) ----
    const float* kb = keys + ((size_t)b * TT + t0) * EE;
    #pragma unroll 4
    for (int idx = tid; idx < npad * 32; idx += NTHREADS) {
        const int r  = idx >> 5;
        const int c4 = idx & 31;
        float4 v = make_float4(0.f, 0.f, 0.f, 0.f);
        if (r < rows) v = __ldg((const float4*)(kb + r * EE) + c4);
        v.x = to_tf32(v.x); v.y = to_tf32(v.y);
        v.z = to_tf32(v.z); v.w = to_tf32(v.w);
        *(float4*)(as_ + r * 132 + c4 * 4) = v;
    }

    // ---- B fragments from prepped streams: Bf = tf32(bc + q*d) ----
    #pragma unroll 4
    for (int idx = tid; idx < 2048; idx += NTHREADS) {
        const float4 bc = __ldg(g_bcF + idx);
        const float4 dd = __ldg(g_dF  + idx);
        const int e0 = ((idx >> 7) << 3) | (idx & 3);
        const float q0 = q_s[e0], q1 = q_s[e0 + 4];
        float4 v;
        v.x = to_tf32(fmaf(q0, dd.x, bc.x));
        v.y = to_tf32(fmaf(q1, dd.y, bc.y));
        v.z = to_tf32(fmaf(q0, dd.z, bc.z));
        v.w = to_tf32(fmaf(q1, dd.w, bc.w));
        *(float4*)(bf + idx * 4) = v;
    }

    // ---- A partials: A[h] = b0[h] + q . (W0a[:,h] + W0c[:,h]) ----
    {
        const int h = tid & 63;
        const int p = tid >> 6;
        float s = 0.f;
        #pragma unroll 8
        for (int e = p * 32; e < p * 32 + 32; ++e)
            s = fmaf(q_s[e], __ldg(g_ac + e * 64 + h), s);
        ap[p * 64 + h] = s;
    }
    __syncthreads();
    if (tid < HH)
        aw[tid] = make_float2(__ldg(b0v + tid) + ap[tid] + ap[64 + tid]
                              + ap[128 + tid] + ap[192 + tid],
                              __ldg(W1 + tid));
    __syncthreads();

    // ---- compute: one m16 block per warp ----
    const int wid = tid >> 5;
    const int lid = tid & 31;
    if (wid < nblk) {
        const int g  = lid >> 2;
        const int tg = lid & 3;
        const int m0 = wid * 16;

        float acc[8][4];
        #pragma unroll
        for (int j = 0; j < 8; ++j)
            #pragma unroll
            for (int i = 0; i < 4; ++i) acc[j][i] = 0.f;

        const uint32_t* asu = (const uint32_t*)as_;
        const uint32_t* bfu = (const uint32_t*)bf;
        const int rowA = (m0 + g) * 132;

        #pragma unroll
        for (int k = 0; k < 16; ++k) {
            uint32_t a[4];
            const int col = k * 8 + tg;
            a[0] = asu[rowA + col];
            a[1] = asu[rowA + 8 * 132 + col];
            a[2] = asu[rowA + col + 4];
            a[3] = asu[rowA + 8 * 132 + col + 4];
            #pragma unroll
            for (int p = 0; p < 4; ++p) {
                const uint4 bv = *(const uint4*)(bfu + ((k * 4 + p) * 32 + lid) * 4);
                mma8(acc[2 * p],     a, bv.x, bv.y);
                mma8(acc[2 * p + 1], a, bv.z, bv.w);
            }
        }

        // ---- fused epilogue ----
        const float bias1 = __ldg(b1v);
        float s0 = bias1, s1 = bias1;
        #pragma unroll
        for (int j = 0; j < 8; ++j) {
            const int h = j * 8 + 2 * tg;
            const float2 w0 = aw[h];
            const float2 w1 = aw[h + 1];
            s0 = fmaf(fmaxf(acc[j][0] + w0.x, 0.f), w0.y, s0);
            s0 = fmaf(fmaxf(acc[j][1] + w1.x, 0.f), w1.y, s0);
            s1 = fmaf(fmaxf(acc[j][2] + w0.x, 0.f), w0.y, s1);
            s1 = fmaf(fmaxf(acc[j][3] + w1.x, 0.f), w1.y, s1);
        }
        s0 += __shfl_xor_sync(0xffffffffu, s0, 1);
        s0 += __shfl_xor_sync(0xffffffffu, s0, 2);
        s1 += __shfl_xor_sync(0xffffffffu, s1, 1);
        s1 += __shfl_xor_sync(0xffffffffu, s1, 2);
        if (tg == 0) {
            const int t = t0 + m0 + g;
            if (t < TT)     out[(size_t)b * TT + t]     = s0;
            if (t + 8 < TT) out[(size_t)b * TT + t + 8] = s1;
        }
    }
}

extern "C" void kernel_launch(void* const* d_in, const int* in_sizes, int n_in,
                              void* d_out, int out_size)
{
    const float* query = (const float*)d_in[0];
    const float* keys  = (const float*)d_in[1];
    const float* W0    = (const float*)d_in[2];
    const float* b0    = (const float*)d_in[3];
    const float* W1    = (const float*)d_in[4];
    const float* b1    = (const float*)d_in[5];
    float* out = (float*)d_out;

    cudaFuncSetAttribute(lau_mma_kernel,
                         cudaFuncAttributeMaxDynamicSharedMemorySize, SMEM_BYTES);

    prep_kernel<<<32, 256>>>(W0);
    lau_mma_kernel<<<2 * BB, NTHREADS, SMEM_BYTES>>>(query, keys, b0, W1, b1, out);
}